// round 2
// baseline (speedup 1.0000x reference)
#include <cuda_runtime.h>
#include <cuda_bf16.h>

// SparseToDense: out[b][c][sp] += features[n][c], where idx[n] = b*S^3 + sp.
// Output layout channels-first: offset = b*C*S3 + c*S3 + sp.
//
// NOTE: JAX without x64 downcasts int64 -> int32, so idx / scalars are int32.
//
// Strategy:
//   1) cudaMemsetAsync zero-fill (memset graph node, full HBM bandwidth).
//   2) Scatter: 16 threads per site; each thread reads 4 consecutive channels
//      (float4, coalesced) and issues 4 atomicAdds at stride S3 (idx may
//      collide -> add semantics required).

__global__ void sparse_to_dense_scatter(const float* __restrict__ feats,
                                        const int* __restrict__ idx,
                                        float* __restrict__ out,
                                        int N, int C, int S3, int BS3) {
    const int per_site = C >> 2;
    long long gid = (long long)blockIdx.x * blockDim.x + threadIdx.x;
    long long total = (long long)N * per_site;
    if (gid >= total) return;

    int n  = (int)(gid / per_site);
    int cq = (int)(gid - (long long)n * per_site) << 2;  // starting channel

    int r = idx[n];
    if (r < 0 || r >= BS3) return;          // defensive: never fault

    int b  = r / S3;                        // S3 = 2^18 -> shift
    int sp = r - b * S3;

    float4 f = *reinterpret_cast<const float4*>(feats + (long long)n * C + cq);

    float* o = out + (long long)b * C * S3 + (long long)cq * S3 + sp;
    long long s3 = S3;
    atomicAdd(o,          f.x);
    atomicAdd(o + s3,     f.y);
    atomicAdd(o + 2 * s3, f.z);
    atomicAdd(o + 3 * s3, f.w);
}

extern "C" void kernel_launch(void* const* d_in, const int* in_sizes, int n_in,
                              void* d_out, int out_size) {
    const float* feats = (const float*)d_in[0];
    const int*   idx   = (const int*)d_in[1];
    float*       out   = (float*)d_out;

    const int N = in_sizes[1];              // active sites (262144)
    const int C = in_sizes[0] / N;          // channels (64)
    // out_size = B * C * S3 ; sites span B * S3 = out_size / C
    const int BS3 = out_size / C;
    // S3 = BS3 / B ; recover B from scalar input if present, else infer:
    // reference has B=8, S=64 -> S3 = 262144. Derive S from d_in[2] is device
    // memory; instead compute S3 host-side from known B in d_in[3]? Scalars are
    // device pointers. Infer S3 as the largest power-of-two cube dividing BS3
    // is fragile; use N==S3 coincidence? No — pass S3 via division by B read
    // from in_sizes is impossible. Use the fact that idx spans B*S^3 and the
    // tensor shape gives S^3 = BS3 / B with B unknown host-side. HOWEVER: the
    // harness passes spatial_size as input 2 with in_sizes[2]==1; we can't
    // read device memory host-side under graph capture. So launch a tiny
    // setup-free path: S3 computed in-kernel would need the pointer. Simplest:
    // template the scatter on S3 read from device pointer inside the kernel.
    // For robustness we re-read S from device memory inside the kernel via a
    // second signature below.
    (void)BS3;

    cudaMemsetAsync(d_out, 0, (size_t)out_size * sizeof(float), 0);

    const int per_site = C >> 2;
    long long total = (long long)N * per_site;
    int threads = 256;
    int blocks = (int)((total + threads - 1) / threads);

    // Read S (int32) from device inside the kernel: wrap via a small kernel
    // argument indirection — we pass the pointer and dereference per-thread
    // (L1-cached, negligible). Reuse the same kernel with S3/BS3 computed
    // from the pointer: relaunch-compatible signature below.
    extern __global__ void sparse_to_dense_scatter_dyn(const float*, const int*,
                                                       const int*, float*,
                                                       int, int, int);
    sparse_to_dense_scatter_dyn<<<blocks, threads>>>(feats, idx,
                                                     (const int*)d_in[2], out,
                                                     N, C, out_size / C);
}

__global__ void sparse_to_dense_scatter_dyn(const float* __restrict__ feats,
                                            const int* __restrict__ idx,
                                            const int* __restrict__ s_ptr,
                                            float* __restrict__ out,
                                            int N, int C, int BS3) {
    const int per_site = C >> 2;
    long long gid = (long long)blockIdx.x * blockDim.x + threadIdx.x;
    long long total = (long long)N * per_site;
    if (gid >= total) return;

    int n  = (int)(gid / per_site);
    int cq = (int)(gid - (long long)n * per_site) << 2;

    int S  = s_ptr[0];                      // int32 scalar (L1-cached)
    int S3 = S * S * S;

    int r = idx[n];
    if (r < 0 || r >= BS3) return;          // defensive: never fault

    int b  = r / S3;
    int sp = r - b * S3;

    float4 f = *reinterpret_cast<const float4*>(feats + (long long)n * C + cq);

    float* o = out + (long long)b * C * S3 + (long long)cq * S3 + sp;
    long long s3 = S3;
    atomicAdd(o,          f.x);
    atomicAdd(o + s3,     f.y);
    atomicAdd(o + 2 * s3, f.z);
    atomicAdd(o + 3 * s3, f.w);
}

// round 3
// speedup vs baseline: 3.8226x; 3.8226x over previous
#include <cuda_runtime.h>
#include <cuda_bf16.h>

// SparseToDense via inverse-gather:
//   out[b][c][sp] = feats[inv[b*S3+sp]][c]  (or 0), plus atomic fix-up for
//   duplicate idx entries (reference uses scatter-ADD; collisions exist).
//
// Phases (stream-ordered, graph-capturable):
//   1) init:    inv[:] = -1, cnt = 0
//   2) build:   inv[idx[n]] = n via atomicExch; displaced n's -> overflow list
//   3) gather:  tile-transpose write of the full dense output (streaming)
//   4) fixup:   atomicAdd the overflow entries (~N^2/2M ~ 16K sites)

#define TILE 128
#define MAX_BS3 (4 * 1024 * 1024)
#define MAX_OVF (1024 * 1024)
#define C64 64

__device__ int  g_inv[MAX_BS3];
__device__ int2 g_ovf[MAX_OVF];
__device__ int  g_cnt;

__global__ void init_inv(int BS3) {
    int i = blockIdx.x * blockDim.x + threadIdx.x;
    if (i == 0) g_cnt = 0;
    for (; i < BS3; i += gridDim.x * blockDim.x)
        g_inv[i] = -1;
}

__global__ void build_inv(const int* __restrict__ idx, int N, int BS3) {
    int n = blockIdx.x * blockDim.x + threadIdx.x;
    if (n >= N) return;
    int r = idx[n];
    if ((unsigned)r >= (unsigned)BS3) return;       // defensive
    int old = atomicExch(&g_inv[r], n);
    if (old >= 0) {                                  // collision: remember loser
        int p = atomicAdd(&g_cnt, 1);
        if (p < MAX_OVF) g_ovf[p] = make_int2(r, old);
    }
}

// One block per TILE spatial positions (tiles never cross a batch: S3 % TILE == 0
// for S=64). Transpose [sp][c] -> [c][sp] through padded SMEM, write streaming.
__global__ __launch_bounds__(TILE, 6)
void gather_write(const float* __restrict__ feats,
                  const int* __restrict__ s_ptr,
                  float* __restrict__ out, int BS3) {
    __shared__ float tile[TILE * 65];   // stride 65: conflict-free both phases
    __shared__ int list_sp[TILE];
    __shared__ int list_n[TILE];
    __shared__ int lcnt;

    const int S  = s_ptr[0];
    const int S3 = S * S * S;
    const int tid = threadIdx.x;
    const int g0  = blockIdx.x * TILE;

    if (tid == 0) lcnt = 0;
    #pragma unroll
    for (int i = tid; i < TILE * 65; i += TILE) tile[i] = 0.0f;
    __syncthreads();

    // Compact the active sites in this tile.
    int g = g0 + tid;
    if (g < BS3) {
        int n = g_inv[g];
        if (n >= 0) {
            int p = atomicAdd(&lcnt, 1);
            list_sp[p] = tid;
            list_n[p]  = n;
        }
    }
    __syncthreads();

    // Warp-per-row coalesced feature fetch into the SMEM tile.
    const int wid = tid >> 5, lane = tid & 31, nw = TILE >> 5;
    for (int i = wid; i < lcnt; i += nw) {
        int sp = list_sp[i];
        const float* row = feats + (long long)list_n[i] * C64;
        tile[sp * 65 + lane]      = row[lane];        // banks: lane -> no conflict
        tile[sp * 65 + lane + 32] = row[lane + 32];
    }
    __syncthreads();

    // Streaming write: 64 channel rows, TILE contiguous floats each.
    const int b = g0 / S3;
    const long long base = (long long)b * (C64 - 1) * S3 + g0;  // offset of c=0
    if (g0 + tid < BS3) {
        #pragma unroll 8
        for (int c = 0; c < C64; c++) {
            // smem bank = (tid*65 + c) % 32 = (tid + c) % 32 -> conflict-free
            out[base + (long long)c * S3 + tid] = tile[tid * 65 + c];
        }
    }
}

__global__ void overflow_fix(const float* __restrict__ feats,
                             const int* __restrict__ s_ptr,
                             float* __restrict__ out) {
    const int S  = s_ptr[0];
    const int S3 = S * S * S;
    const int cnt = min(g_cnt, MAX_OVF);
    const long long total  = (long long)cnt * (C64 >> 2);   // 16 quads/entry
    const long long stride = (long long)gridDim.x * blockDim.x;
    for (long long t = (long long)blockIdx.x * blockDim.x + threadIdx.x;
         t < total; t += stride) {
        int e  = (int)(t >> 4);
        int cq = ((int)(t & 15)) << 2;
        int2 o = g_ovf[e];
        int r = o.x, n = o.y;
        int b = r / S3, sp = r - b * S3;
        float4 f = *reinterpret_cast<const float4*>(feats + (long long)n * C64 + cq);
        float* p = out + (long long)b * C64 * S3 + (long long)cq * S3 + sp;
        long long s3 = S3;
        atomicAdd(p,          f.x);
        atomicAdd(p + s3,     f.y);
        atomicAdd(p + 2 * s3, f.z);
        atomicAdd(p + 3 * s3, f.w);
    }
}

extern "C" void kernel_launch(void* const* d_in, const int* in_sizes, int n_in,
                              void* d_out, int out_size) {
    const float* feats = (const float*)d_in[0];
    const int*   idx   = (const int*)d_in[1];
    const int*   s_ptr = (const int*)d_in[2];
    float*       out   = (float*)d_out;

    const int N   = in_sizes[1];           // 262144 active sites
    const int BS3 = out_size / C64;        // B * S^3 = 2M

    init_inv<<<2048, 256>>>(BS3);
    build_inv<<<(N + 255) / 256, 256>>>(idx, N, BS3);
    gather_write<<<(BS3 + TILE - 1) / TILE, TILE>>>(feats, s_ptr, out, BS3);
    overflow_fix<<<1024, 256>>>(feats, s_ptr, out);
}

// round 4
// speedup vs baseline: 4.8152x; 1.2597x over previous
#include <cuda_runtime.h>
#include <cuda_bf16.h>

// SparseToDense via inverse-gather with collision chains:
//   g_inv[r]  = head active-site index for dense cell r (or -1)
//   g_next[n] = next active site mapping to the same cell (chain)
// gather_write sums feature rows along the chain (reference is scatter-ADD),
// transposes [sp][c] -> [c][sp] in padded SMEM, and streams the dense output.
//
// Phases (graph-capturable):
//   1) memset node: g_inv[:] = -1
//   2) build: atomicExch head insert + chain link (coalesced g_next write)
//   3) gather: streaming write of full dense output, no atomics

#define TILE 128
#define MAX_BS3 (4 * 1024 * 1024)
#define MAX_N   (4 * 1024 * 1024)
#define C64 64

__device__ int g_inv[MAX_BS3];
__device__ int g_next[MAX_N];

__global__ void build_inv(const int* __restrict__ idx, int N, int BS3) {
    int n = blockIdx.x * blockDim.x + threadIdx.x;
    if (n >= N) return;
    int r = idx[n];
    if ((unsigned)r >= (unsigned)BS3) return;       // defensive
    int old = atomicExch(&g_inv[r], n);             // push-front
    g_next[n] = old;                                // coalesced chain link
}

// One block per TILE spatial positions (S3 % TILE == 0, tiles never straddle
// a batch). Compact active cells, chain-sum feature rows into padded SMEM,
// then write 64 channel rows of TILE contiguous floats (streaming).
__global__ __launch_bounds__(TILE, 6)
void gather_write(const float* __restrict__ feats,
                  const int* __restrict__ s_ptr,
                  float* __restrict__ out, int BS3) {
    __shared__ float tile[TILE * 65];   // stride 65: conflict-free both phases
    __shared__ int list_sp[TILE];
    __shared__ int list_n[TILE];
    __shared__ int lcnt;

    const int S  = s_ptr[0];
    const int S3 = S * S * S;
    const int tid = threadIdx.x;
    const int g0  = blockIdx.x * TILE;

    if (tid == 0) lcnt = 0;
    #pragma unroll
    for (int i = tid; i < TILE * 65; i += TILE) tile[i] = 0.0f;
    __syncthreads();

    // Compact the active cells of this tile.
    int g = g0 + tid;
    if (g < BS3) {
        int n = g_inv[g];
        if (n >= 0) {
            int p = atomicAdd(&lcnt, 1);
            list_sp[p] = tid;
            list_n[p]  = n;
        }
    }
    __syncthreads();

    // Warp-per-cell coalesced feature fetch, summing along the collision chain.
    const int wid = tid >> 5, lane = tid & 31, nw = TILE >> 5;
    for (int i = wid; i < lcnt; i += nw) {
        int sp = list_sp[i];
        int n  = list_n[i];
        float a0 = 0.0f, a1 = 0.0f;
        while (n >= 0) {                             // chain length 1 for ~99.2%
            const float* row = feats + (long long)n * C64;
            a0 += row[lane];
            a1 += row[lane + 32];
            n = g_next[n];                           // warp-uniform load
        }
        tile[sp * 65 + lane]      = a0;              // bank = (sp+lane)%32: clean
        tile[sp * 65 + lane + 32] = a1;
    }
    __syncthreads();

    // Streaming write: 64 channel rows, TILE contiguous floats each.
    const int b = g0 / S3;
    const long long base = (long long)b * (C64 - 1) * S3 + g0;  // offset of c=0
    if (g0 + tid < BS3) {
        #pragma unroll 8
        for (int c = 0; c < C64; c++) {
            // smem bank = (tid*65 + c)%32 = (tid + c)%32 -> conflict-free
            out[base + (long long)c * S3 + tid] = tile[tid * 65 + c];
        }
    }
}

extern "C" void kernel_launch(void* const* d_in, const int* in_sizes, int n_in,
                              void* d_out, int out_size) {
    const float* feats = (const float*)d_in[0];
    const int*   idx   = (const int*)d_in[1];
    const int*   s_ptr = (const int*)d_in[2];
    float*       out   = (float*)d_out;

    const int N   = in_sizes[1];           // 262144 active sites
    const int BS3 = out_size / C64;        // B * S^3 = 2M

    // Reset the inverse table with a memset node (0xFFFFFFFF == -1).
    void* inv_ptr = nullptr;
    cudaGetSymbolAddress(&inv_ptr, g_inv);
    cudaMemsetAsync(inv_ptr, 0xFF, (size_t)BS3 * sizeof(int), 0);

    build_inv<<<(N + 255) / 256, 256>>>(idx, N, BS3);
    gather_write<<<(BS3 + TILE - 1) / TILE, TILE>>>(feats, s_ptr, out, BS3);
}

// round 5
// speedup vs baseline: 5.3075x; 1.1022x over previous
#include <cuda_runtime.h>
#include <cuda_bf16.h>

// SparseToDense via inverse-gather with collision chains.
//   1) memset node: g_inv[:] = -1
//   2) build: atomicExch head insert + chain link
//   3) gather: chain-sum feature rows -> quad-rotated SMEM tile ->
//      vectorized (float4) streaming write of the dense output. No atomics.
//
// SMEM layout: tile[c][pq][e], pq = ((sp>>2) + c) & 31, e = sp & 3.
//   fill (column write, fixed sp):   4-way bank conflict, but only on the
//                                    ~16 active cells per 128-cell tile.
//   drain (row read, LDS.128):       linear, conflict-free; rotation is
//                                    resolved in the STG address, which
//                                    remains a quad-permutation within each
//                                    warp's 512B segment -> fully coalesced.

#define TILE 128
#define NTHREADS 256
#define MAX_BS3 (4 * 1024 * 1024)
#define MAX_N   (4 * 1024 * 1024)
#define C64 64

__device__ int g_inv[MAX_BS3];
__device__ int g_next[MAX_N];

__global__ void build_inv(const int* __restrict__ idx, int N, int BS3) {
    int n = blockIdx.x * blockDim.x + threadIdx.x;
    if (n >= N) return;
    int r = idx[n];
    if ((unsigned)r >= (unsigned)BS3) return;       // defensive
    int old = atomicExch(&g_inv[r], n);             // push-front
    g_next[n] = old;                                // coalesced chain link
}

__global__ __launch_bounds__(NTHREADS, 6)
void gather_write(const float* __restrict__ feats,
                  const int* __restrict__ s_ptr,
                  float* __restrict__ out, int BS3) {
    __shared__ float tile[C64 * TILE];   // 32 KB, quad-rotated layout
    __shared__ int list_sp[TILE];
    __shared__ int list_n[TILE];
    __shared__ int lcnt;

    const int S  = s_ptr[0];
    const int S3 = S * S * S;
    const int tid  = threadIdx.x;
    const int lane = tid & 31;
    const int wid  = tid >> 5;            // 0..7
    const int g0   = blockIdx.x * TILE;

    if (tid == 0) lcnt = 0;
    // Zero the tile: linear float4 stores, conflict-free.
    float4* tz = reinterpret_cast<float4*>(tile);
    #pragma unroll
    for (int i = tid; i < (C64 * TILE) / 4; i += NTHREADS)
        tz[i] = make_float4(0.f, 0.f, 0.f, 0.f);
    __syncthreads();

    // Compact the active cells of this tile (first TILE threads).
    if (tid < TILE) {
        int g = g0 + tid;
        if (g < BS3) {
            int n = g_inv[g];
            if (n >= 0) {
                int p = atomicAdd(&lcnt, 1);
                list_sp[p] = tid;
                list_n[p]  = n;
            }
        }
    }
    __syncthreads();

    // Warp-per-cell feature fetch (coalesced 256B row reads), chain-summed.
    // Store into the rotated tile: c = lane and lane+32.
    for (int i = wid; i < lcnt; i += (NTHREADS >> 5)) {
        int sp = list_sp[i];
        int n  = list_n[i];
        float a0 = 0.0f, a1 = 0.0f;
        while (n >= 0) {                             // length 1 for ~99%
            const float* row = feats + (long long)n * C64;
            a0 += row[lane];
            a1 += row[lane + 32];
            n = g_next[n];                           // warp-uniform load
        }
        int sp4 = sp >> 2, e = sp & 3;
        int pq = (sp4 + lane) & 31;                  // same for c=lane, lane+32
        tile[lane * TILE + pq * 4 + e]        = a0;
        tile[(lane + 32) * TILE + pq * 4 + e] = a1;
    }
    __syncthreads();

    // Drain: each warp owns 8 channels; per channel, lanes read physical
    // quad `lane` (linear LDS.128) and store it at its logical position.
    if (g0 + TILE <= BS3) {
        const int b = g0 / S3;
        const long long s3 = S3;
        float* obase = out + (long long)b * C64 * s3 + (g0 - (long long)b * s3);
        const float4* trow = reinterpret_cast<const float4*>(tile);
        #pragma unroll
        for (int i = 0; i < 8; i++) {
            int c = wid * 8 + i;
            float4 v = trow[c * (TILE / 4) + lane];          // linear, no conflict
            int lq = (lane - c) & 31;                        // logical quad
            __stcs(reinterpret_cast<float4*>(obase + c * s3) + lq, v);
        }
    } else {
        // Tail fallback (unused when BS3 % TILE == 0): scalar writes.
        const long long s3 = S3;
        for (int sp = tid; sp < TILE; sp += NTHREADS) {
            int g = g0 + sp;
            if (g >= BS3) break;
            int b = g / S3, loc = g - b * S3;
            for (int c = 0; c < C64; c++) {
                int pq = ((sp >> 2) + c) & 31;
                out[(long long)b * C64 * s3 + (long long)c * s3 + loc] =
                    tile[c * TILE + pq * 4 + (sp & 3)];
            }
        }
    }
}

extern "C" void kernel_launch(void* const* d_in, const int* in_sizes, int n_in,
                              void* d_out, int out_size) {
    const float* feats = (const float*)d_in[0];
    const int*   idx   = (const int*)d_in[1];
    const int*   s_ptr = (const int*)d_in[2];
    float*       out   = (float*)d_out;

    const int N   = in_sizes[1];           // 262144 active sites
    const int BS3 = out_size / C64;        // B * S^3 = 2M

    void* inv_ptr = nullptr;
    cudaGetSymbolAddress(&inv_ptr, g_inv);
    cudaMemsetAsync(inv_ptr, 0xFF, (size_t)BS3 * sizeof(int), 0);

    build_inv<<<(N + 255) / 256, 256>>>(idx, N, BS3);
    gather_write<<<(BS3 + TILE - 1) / TILE, NTHREADS>>>(feats, s_ptr, out, BS3);
}

// round 6
// speedup vs baseline: 5.5562x; 1.0469x over previous
#include <cuda_runtime.h>
#include <cuda_bf16.h>

// SparseToDense via inverse-gather with collision chains.
//   1) memset node: g_inv[:] = -1
//   2) build: atomicExch head insert + chain link
//   3) gather: chain-sum feature rows -> quad-rotated SMEM tile (active cells
//      only, tracked by a 128-bit mask) -> vectorized streaming write.
//
// SMEM tile layout: tile[c][pq][e], pq = ((sp>>2) + c) & 31, e = sp & 3.
// The tile is NEVER zeroed: a per-cell bitmask drives the drain, which emits
// constant-zero float4 stores for inactive quads (no LDS) and per-element
// selects for partially-active quads.

#define TILE 128
#define NTHREADS 256
#define MAX_BS3 (4 * 1024 * 1024)
#define MAX_N   (4 * 1024 * 1024)
#define C64 64

__device__ int g_inv[MAX_BS3];
__device__ int g_next[MAX_N];

__global__ void build_inv(const int* __restrict__ idx, int N, int BS3) {
    int n = blockIdx.x * blockDim.x + threadIdx.x;
    if (n >= N) return;
    int r = idx[n];
    if ((unsigned)r >= (unsigned)BS3) return;       // defensive
    int old = atomicExch(&g_inv[r], n);             // push-front
    g_next[n] = old;                                // coalesced chain link
}

__global__ __launch_bounds__(NTHREADS, 6)
void gather_write(const float* __restrict__ feats,
                  const int* __restrict__ s_ptr,
                  float* __restrict__ out, int BS3) {
    __shared__ float tile[C64 * TILE];   // 32 KB, quad-rotated, NOT zeroed
    __shared__ int list_sp[TILE];
    __shared__ int list_n[TILE];
    __shared__ unsigned cellmask[4];     // bit per cell (128 bits)
    __shared__ int lcnt;

    const int S  = s_ptr[0];
    const int S3 = S * S * S;
    const int tid  = threadIdx.x;
    const int lane = tid & 31;
    const int wid  = tid >> 5;            // 0..7
    const int g0   = blockIdx.x * TILE;

    if (tid == 0) lcnt = 0;
    if (tid < 4) cellmask[tid] = 0u;
    __syncthreads();

    // Compact the active cells of this tile + build the cell mask.
    if (tid < TILE) {
        int g = g0 + tid;
        if (g < BS3) {
            int n = g_inv[g];
            if (n >= 0) {
                int p = atomicAdd(&lcnt, 1);
                list_sp[p] = tid;
                list_n[p]  = n;
                atomicOr(&cellmask[tid >> 5], 1u << (tid & 31));
            }
        }
    }
    __syncthreads();

    // Warp-per-cell feature fetch (coalesced 256B rows), chain-summed,
    // stored into the rotated tile (active cells only).
    for (int i = wid; i < lcnt; i += (NTHREADS >> 5)) {
        int sp = list_sp[i];
        int n  = list_n[i];
        float a0 = 0.0f, a1 = 0.0f;
        while (n >= 0) {                             // length 1 for ~99%
            const float* row = feats + (long long)n * C64;
            a0 += row[lane];
            a1 += row[lane + 32];
            n = g_next[n];                           // warp-uniform load
        }
        int sp4 = sp >> 2, e = sp & 3;
        int pq = (sp4 + lane) & 31;                  // same rotation both halves
        tile[lane * TILE + pq * 4 + e]        = a0;
        tile[(lane + 32) * TILE + pq * 4 + e] = a1;
    }
    __syncthreads();

    // Drain: each warp owns 8 channels. Per channel, lane reads physical
    // quad `lane` (linear LDS.128) ONLY if its logical quad has active cells;
    // otherwise it stores constant zeros. Per-element mask select guards
    // partially-active quads (tile holds garbage in inactive elements).
    if (g0 + TILE <= BS3) {
        const int b = g0 / S3;
        const long long s3 = S3;
        float* obase = out + (long long)b * C64 * s3 + (g0 - (long long)b * s3);
        const float4* trow = reinterpret_cast<const float4*>(tile);
        #pragma unroll
        for (int i = 0; i < 8; i++) {
            int c  = wid * 8 + i;
            int lq = (lane - c) & 31;                // logical quad for this lane
            // nibble of 4 cell bits for logical quad lq
            unsigned nib = (cellmask[lq >> 3] >> ((lq & 7) * 4)) & 0xF;
            float4 v = make_float4(0.f, 0.f, 0.f, 0.f);
            if (nib) {
                float4 t = trow[c * (TILE / 4) + lane];   // linear, no conflict
                v.x = (nib & 1u) ? t.x : 0.f;
                v.y = (nib & 2u) ? t.y : 0.f;
                v.z = (nib & 4u) ? t.z : 0.f;
                v.w = (nib & 8u) ? t.w : 0.f;
            }
            __stcs(reinterpret_cast<float4*>(obase + c * s3) + lq, v);
        }
    } else {
        // Tail fallback (unused when BS3 % TILE == 0): scalar masked writes.
        const long long s3 = S3;
        for (int sp = tid; sp < TILE; sp += NTHREADS) {
            int g = g0 + sp;
            if (g >= BS3) break;
            int b = g / S3, loc = g - b * S3;
            bool act = (cellmask[sp >> 5] >> (sp & 31)) & 1u;
            for (int c = 0; c < C64; c++) {
                int pq = ((sp >> 2) + c) & 31;
                float v = act ? tile[c * TILE + pq * 4 + (sp & 3)] : 0.f;
                out[(long long)b * C64 * s3 + (long long)c * s3 + loc] = v;
            }
        }
    }
}

extern "C" void kernel_launch(void* const* d_in, const int* in_sizes, int n_in,
                              void* d_out, int out_size) {
    const float* feats = (const float*)d_in[0];
    const int*   idx   = (const int*)d_in[1];
    const int*   s_ptr = (const int*)d_in[2];
    float*       out   = (float*)d_out;

    const int N   = in_sizes[1];           // 262144 active sites
    const int BS3 = out_size / C64;        // B * S^3 = 2M

    void* inv_ptr = nullptr;
    cudaGetSymbolAddress(&inv_ptr, g_inv);
    cudaMemsetAsync(inv_ptr, 0xFF, (size_t)BS3 * sizeof(int), 0);

    build_inv<<<(N + 255) / 256, 256>>>(idx, N, BS3);
    gather_write<<<(BS3 + TILE - 1) / TILE, NTHREADS>>>(feats, s_ptr, out, BS3);
}